// round 1
// baseline (speedup 1.0000x reference)
#include <cuda_runtime.h>

// Help_36567351558250: fused 3DGS covariance-axes kernel.
// Inputs (metadata order): rot (N,4) f32, mod (1,) f32, scale (N,2) f32,
//                          p_k (N,3) f32, view_matrix (N,16) f32
// Output: A (N,9) f32
//
// Pure HBM-streaming: 136 B/row, 2M rows => ~272 MB. Design for max
// load/store coalescing; SMEM-stage the 9-float rows so global stores are
// stride-1 (one 128B line per warp STG).

#define TPB 256

__global__ __launch_bounds__(TPB) void gs_cov_kernel(
    const float4* __restrict__ rot,      // N x 4
    const float*  __restrict__ mod,      // 1
    const float2* __restrict__ scale,    // N x 2
    const float*  __restrict__ p_k,      // N x 3
    const float4* __restrict__ vm4,      // N x 16 viewed as N*4 float4
    float*        __restrict__ out,      // N x 9
    int N)
{
    __shared__ float sbuf[TPB * 9];

    const int t   = threadIdx.x;
    const int row = blockIdx.x * TPB + t;

    if (row < N) {
        // ---- loads (front-batched for MLP) ----
        const float4 q  = rot[row];
        const float2 sc = scale[row];
        const float4 c0 = vm4[row * 4 + 0];   // vm[0..3]
        const float4 c1 = vm4[row * 4 + 1];   // vm[4..7]
        const float4 c2 = vm4[row * 4 + 2];   // vm[8..11]
        const float4 c3 = vm4[row * 4 + 3];   // vm[12..15]
        const float  p0 = p_k[row * 3 + 0];
        const float  p1 = p_k[row * 3 + 1];
        const float  p2 = p_k[row * 3 + 2];
        const float  m  = __ldg(mod);

        // ---- quaternion -> rotation columns ----
        const float r = q.x, x = q.y, y = q.z, z = q.w;
        const float R00 = 1.0f - 2.0f * (y * y + z * z);
        const float R10 = 2.0f * (x * y + r * z);
        const float R20 = 2.0f * (x * z - r * y);
        const float R01 = 2.0f * (x * y - r * z);
        const float R11 = 1.0f - 2.0f * (x * x + z * z);
        const float R21 = 2.0f * (y * z + r * x);

        const float s0 = m * sc.x;
        const float s1 = m * sc.y;
        const float u0 = s0 * R00, u1 = s0 * R10, u2 = s0 * R20;
        const float v0 = s1 * R01, v1 = s1 * R11, v2 = s1 * R21;

        // ---- view-matrix rows dot axes / point ----
        const float r1s1 = c0.x * u0 + c1.x * u1 + c2.x * u2;
        const float r1s2 = c0.x * v0 + c1.x * v1 + c2.x * v2;
        const float r2s1 = c0.y * u0 + c1.y * u1 + c2.y * u2;
        const float r2s2 = c0.y * v0 + c1.y * v1 + c2.y * v2;
        const float r3s1 = c0.z * u0 + c1.z * u1 + c2.z * u2;
        const float r3s2 = c0.z * v0 + c1.z * v1 + c2.z * v2;

        const float r1p = c0.x * p0 + c1.x * p1 + c2.x * p2 + c3.x;
        const float r2p = c0.y * p0 + c1.y * p1 + c2.y * p2 + c3.y;
        const float r3p = c0.z * p0 + c1.z * p1 + c2.z * p2 + c3.z;

        // stride-9 SMEM writes: gcd(9,32)=1 -> conflict-free within warp
        float* s = &sbuf[t * 9];
        s[0] = r1s1; s[1] = r1s2; s[2] = r1p;
        s[3] = r2s1; s[4] = r2s2; s[5] = r2p;
        s[6] = r3s1; s[7] = r3s2; s[8] = r3p;
    }
    __syncthreads();

    // ---- coalesced writeback: 9 stride-1 STG.32 per thread ----
    const int base = blockIdx.x * (TPB * 9);
    const int nOut = N * 9;
    #pragma unroll
    for (int k = 0; k < 9; k++) {
        const int gi = base + k * TPB + t;
        if (gi < nOut) out[gi] = sbuf[k * TPB + t];
    }
}

extern "C" void kernel_launch(void* const* d_in, const int* in_sizes, int n_in,
                              void* d_out, int out_size) {
    const float4* rot   = (const float4*)d_in[0];
    const float*  mod   = (const float*)d_in[1];
    const float2* scale = (const float2*)d_in[2];
    const float*  p_k   = (const float*)d_in[3];
    const float4* vm4   = (const float4*)d_in[4];
    float*        out   = (float*)d_out;

    const int N = in_sizes[0] / 4;   // rot has N*4 elements
    const int blocks = (N + TPB - 1) / TPB;
    gs_cov_kernel<<<blocks, TPB>>>(rot, mod, scale, p_k, vm4, out, N);
}